// round 7
// baseline (speedup 1.0000x reference)
#include <cuda_runtime.h>

#define BB 8
#define TT 16
#define HH 96
#define WW 96
#define CI 8
#define FF 64

#define NPIX (BB*HH*WW*FF)   // 4,718,592 floats per state buffer

#define SH_STRIDE 68         // 68 mod 32 == 4 -> conflict-free LDS.128 phases
#define SX_STRIDE 12         // 12 mod 32 -> conflict-free for 8-lane phases

__device__ float g_h0[NPIX];
__device__ float g_h1[NPIX];
__device__ float g_c[NPIX];

__device__ __forceinline__ float hsig(float z) {
    return fminf(fmaxf(fmaf(z, 0.2f, 0.5f), 0.0f), 1.0f);
}

__global__ void zero_kernel(float* a, float* b, int n4) {
    int i = blockIdx.x * blockDim.x + threadIdx.x;
    float4 z = make_float4(0.f, 0.f, 0.f, 0.f);
    if (i < n4) {
        ((float4*)a)[i] = z;
        ((float4*)b)[i] = z;
    }
}

// One ConvLSTM step. Block = 8x8 pixel tile, 256 threads.
// Thread (pg, cg): pg = tid&15 -> 4 pixels {pg, pg+16, pg+32, pg+48} of the 64-pixel
// tile (same column, rows py0+2u); cg = tid>>4 -> filters fb..fb+3 (fb = cg*4),
// across all 4 gates (channels q*64+fb+j). 64 accumulators/thread.
// Each weight float4 load feeds 16 FMAs (4 pixels x 4 channels) -> FMA-bound.
__global__ __launch_bounds__(256, 2)
void step_kernel(const float* __restrict__ x,
                 const float* __restrict__ Wx,
                 const float* __restrict__ Wh,
                 const float* __restrict__ bias,
                 const float* __restrict__ h_in,
                 float* __restrict__ c_st,
                 float* __restrict__ h_out,
                 int t)
{
    __shared__ float sh[10 * 10 * SH_STRIDE];   // h halo tile, padded (27.2 KB)
    __shared__ float sx[10 * 10 * SX_STRIDE];   // x halo tile, padded (4.8 KB)

    const int tid = threadIdx.x;
    const int pg  = tid & 15;       // pixel group 0..15
    const int cg  = tid >> 4;       // filter quad 0..15
    const int fb  = cg * 4;         // filter base
    const int py0 = pg >> 3;        // 0..1
    const int px  = pg & 7;         // 0..7
    const int bx0 = blockIdx.x * 8;
    const int by0 = blockIdx.y * 8;
    const int bb  = blockIdx.z;

    // ---- stage h halo: 10x10 pixels x 64 ch = 1600 float4 ----
    for (int i = tid; i < 1600; i += 256) {
        int ch4 = i & 15;
        int pix = i >> 4;
        int r  = pix / 10;
        int cc = pix - r * 10;
        int gy = by0 + r - 1;
        int gx = bx0 + cc - 1;
        float4 v = make_float4(0.f, 0.f, 0.f, 0.f);
        if ((unsigned)gy < 96u && (unsigned)gx < 96u)
            v = __ldg((const float4*)(h_in + ((bb * 96 + gy) * 96 + gx) * 64 + ch4 * 4));
        *(float4*)(sh + pix * SH_STRIDE + ch4 * 4) = v;
    }
    // ---- stage x halo: 10x10 pixels x 8 ch = 200 float4 ----
    for (int i = tid; i < 200; i += 256) {
        int ch4 = i & 1;
        int pix = i >> 1;
        int r  = pix / 10;
        int cc = pix - r * 10;
        int gy = by0 + r - 1;
        int gx = bx0 + cc - 1;
        float4 v = make_float4(0.f, 0.f, 0.f, 0.f);
        if ((unsigned)gy < 96u && (unsigned)gx < 96u)
            v = __ldg((const float4*)(x + (((bb * TT + t) * 96 + gy) * 96 + gx) * 8 + ch4 * 4));
        *(float4*)(sx + pix * SX_STRIDE + ch4 * 4) = v;
    }
    __syncthreads();

    // acc[q][u] = float4 over 4 filters j, for gate q, pixel slot u
    float4 acc[4][4];
    #pragma unroll
    for (int q = 0; q < 4; q++) {
        float4 bv = __ldg((const float4*)(bias + q * 64 + fb));
        #pragma unroll
        for (int u = 0; u < 4; u++) acc[q][u] = bv;
    }

    // ---- input conv: K = 9 * 8 ----
    #pragma unroll 1
    for (int k = 0; k < 9; k++) {
        const int ky = k / 3;
        const int kx = k - ky * 3;
        const float* ab0 = sx + ((py0 + 0 + ky) * 10 + (px + kx)) * SX_STRIDE;
        const float* ab1 = ab0 + 2 * 10 * SX_STRIDE;
        const float* ab2 = ab1 + 2 * 10 * SX_STRIDE;
        const float* ab3 = ab2 + 2 * 10 * SX_STRIDE;
        const float* wkb = Wx + k * 8 * 256 + fb;
        #pragma unroll
        for (int ic0 = 0; ic0 < 8; ic0 += 4) {
            float4 av[4];
            av[0] = *(const float4*)(ab0 + ic0);
            av[1] = *(const float4*)(ab1 + ic0);
            av[2] = *(const float4*)(ab2 + ic0);
            av[3] = *(const float4*)(ab3 + ic0);
            #pragma unroll
            for (int v = 0; v < 4; v++) {
                const float* w = wkb + (ic0 + v) * 256;
                float4 w0 = __ldg((const float4*)(w));
                float4 w1 = __ldg((const float4*)(w + 64));
                float4 w2 = __ldg((const float4*)(w + 128));
                float4 w3 = __ldg((const float4*)(w + 192));
                #pragma unroll
                for (int u = 0; u < 4; u++) {
                    const float a = (v == 0) ? av[u].x : (v == 1) ? av[u].y
                                  : (v == 2) ? av[u].z : av[u].w;
                    acc[0][u].x = fmaf(a, w0.x, acc[0][u].x);
                    acc[0][u].y = fmaf(a, w0.y, acc[0][u].y);
                    acc[0][u].z = fmaf(a, w0.z, acc[0][u].z);
                    acc[0][u].w = fmaf(a, w0.w, acc[0][u].w);
                    acc[1][u].x = fmaf(a, w1.x, acc[1][u].x);
                    acc[1][u].y = fmaf(a, w1.y, acc[1][u].y);
                    acc[1][u].z = fmaf(a, w1.z, acc[1][u].z);
                    acc[1][u].w = fmaf(a, w1.w, acc[1][u].w);
                    acc[2][u].x = fmaf(a, w2.x, acc[2][u].x);
                    acc[2][u].y = fmaf(a, w2.y, acc[2][u].y);
                    acc[2][u].z = fmaf(a, w2.z, acc[2][u].z);
                    acc[2][u].w = fmaf(a, w2.w, acc[2][u].w);
                    acc[3][u].x = fmaf(a, w3.x, acc[3][u].x);
                    acc[3][u].y = fmaf(a, w3.y, acc[3][u].y);
                    acc[3][u].z = fmaf(a, w3.z, acc[3][u].z);
                    acc[3][u].w = fmaf(a, w3.w, acc[3][u].w);
                }
            }
        }
    }

    // ---- recurrent conv: K = 9 * 64 (dominant work) ----
    #pragma unroll 1
    for (int k = 0; k < 9; k++) {
        const int ky = k / 3;
        const int kx = k - ky * 3;
        const float* ab0 = sh + ((py0 + 0 + ky) * 10 + (px + kx)) * SH_STRIDE;
        const float* ab1 = ab0 + 2 * 10 * SH_STRIDE;
        const float* ab2 = ab1 + 2 * 10 * SH_STRIDE;
        const float* ab3 = ab2 + 2 * 10 * SH_STRIDE;
        const float* wkb = Wh + k * 64 * 256 + fb;
        #pragma unroll 2
        for (int ic0 = 0; ic0 < 64; ic0 += 4) {
            float4 av[4];
            av[0] = *(const float4*)(ab0 + ic0);
            av[1] = *(const float4*)(ab1 + ic0);
            av[2] = *(const float4*)(ab2 + ic0);
            av[3] = *(const float4*)(ab3 + ic0);
            #pragma unroll
            for (int v = 0; v < 4; v++) {
                const float* w = wkb + (ic0 + v) * 256;
                float4 w0 = __ldg((const float4*)(w));
                float4 w1 = __ldg((const float4*)(w + 64));
                float4 w2 = __ldg((const float4*)(w + 128));
                float4 w3 = __ldg((const float4*)(w + 192));
                #pragma unroll
                for (int u = 0; u < 4; u++) {
                    const float a = (v == 0) ? av[u].x : (v == 1) ? av[u].y
                                  : (v == 2) ? av[u].z : av[u].w;
                    acc[0][u].x = fmaf(a, w0.x, acc[0][u].x);
                    acc[0][u].y = fmaf(a, w0.y, acc[0][u].y);
                    acc[0][u].z = fmaf(a, w0.z, acc[0][u].z);
                    acc[0][u].w = fmaf(a, w0.w, acc[0][u].w);
                    acc[1][u].x = fmaf(a, w1.x, acc[1][u].x);
                    acc[1][u].y = fmaf(a, w1.y, acc[1][u].y);
                    acc[1][u].z = fmaf(a, w1.z, acc[1][u].z);
                    acc[1][u].w = fmaf(a, w1.w, acc[1][u].w);
                    acc[2][u].x = fmaf(a, w2.x, acc[2][u].x);
                    acc[2][u].y = fmaf(a, w2.y, acc[2][u].y);
                    acc[2][u].z = fmaf(a, w2.z, acc[2][u].z);
                    acc[2][u].w = fmaf(a, w2.w, acc[2][u].w);
                    acc[3][u].x = fmaf(a, w3.x, acc[3][u].x);
                    acc[3][u].y = fmaf(a, w3.y, acc[3][u].y);
                    acc[3][u].z = fmaf(a, w3.z, acc[3][u].z);
                    acc[3][u].w = fmaf(a, w3.w, acc[3][u].w);
                }
            }
        }
    }

    // ---- gate epilogue: i,f,g,o -> c_new, h_new (thread-local) ----
    #pragma unroll
    for (int u = 0; u < 4; u++) {
        const int gy = by0 + py0 + 2 * u;
        const int gx = bx0 + px;
        const int base = ((bb * 96 + gy) * 96 + gx) * 64 + fb;
        float4 cv = *(const float4*)(c_st + base);
        float cin[4] = {cv.x, cv.y, cv.z, cv.w};
        float iv[4] = {acc[0][u].x, acc[0][u].y, acc[0][u].z, acc[0][u].w};
        float fv[4] = {acc[1][u].x, acc[1][u].y, acc[1][u].z, acc[1][u].w};
        float gv[4] = {acc[2][u].x, acc[2][u].y, acc[2][u].z, acc[2][u].w};
        float ov[4] = {acc[3][u].x, acc[3][u].y, acc[3][u].z, acc[3][u].w};
        float cn[4], hn[4];
        #pragma unroll
        for (int j = 0; j < 4; j++) {
            float ig  = hsig(iv[j]);
            float fg_ = hsig(fv[j]);
            float gg  = tanhf(gv[j]);
            float og  = hsig(ov[j]);
            cn[j] = fg_ * cin[j] + ig * gg;
            hn[j] = og * tanhf(cn[j]);
        }
        *(float4*)(c_st + base)  = make_float4(cn[0], cn[1], cn[2], cn[3]);
        *(float4*)(h_out + base) = make_float4(hn[0], hn[1], hn[2], hn[3]);
    }
}

extern "C" void kernel_launch(void* const* d_in, const int* in_sizes, int n_in,
                              void* d_out, int out_size) {
    const float* x    = (const float*)d_in[0];
    const float* Wx   = (const float*)d_in[1];
    const float* Wh   = (const float*)d_in[2];
    const float* bias = (const float*)d_in[3];
    float* out = (float*)d_out;

    float *h0, *h1, *c;
    cudaGetSymbolAddress((void**)&h0, g_h0);
    cudaGetSymbolAddress((void**)&h1, g_h1);
    cudaGetSymbolAddress((void**)&c,  g_c);

    // zero h(0) and c(0) every call (graph replays must be deterministic)
    int n4 = NPIX / 4;
    zero_kernel<<<(n4 + 255) / 256, 256>>>(h0, c, n4);

    dim3 grid(12, 12, BB);   // 12x12 spatial tiles of 8x8, per batch
    for (int t = 0; t < TT; t++) {
        const float* hin = (t & 1) ? h1 : h0;
        float* hout = (t == TT - 1) ? out : ((t & 1) ? h0 : h1);
        step_kernel<<<grid, 256>>>(x, Wx, Wh, bias, hin, c, hout, t);
    }
}

// round 8
// speedup vs baseline: 1.6249x; 1.6249x over previous
#include <cuda_runtime.h>

#define BB 8
#define TT 16
#define HH 96
#define WW 96
#define CI 8
#define FF 64

#define NPIX (BB*HH*WW*FF)   // 4,718,592 floats per state buffer

#define SH_STRIDE 68         // 68 mod 32 == 4 -> conflict-free LDS.128 phases
#define SX_STRIDE 12         // 12 mod 32 -> conflict-free for 8-lane phases

__device__ float g_h0[NPIX];
__device__ float g_h1[NPIX];
__device__ float g_c[NPIX];

__device__ __forceinline__ float hsig(float z) {
    return fminf(fmaxf(fmaf(z, 0.2f, 0.5f), 0.0f), 1.0f);
}

__global__ void zero_kernel(float* a, float* b, int n4) {
    int i = blockIdx.x * blockDim.x + threadIdx.x;
    float4 z = make_float4(0.f, 0.f, 0.f, 0.f);
    if (i < n4) {
        ((float4*)a)[i] = z;
        ((float4*)b)[i] = z;
    }
}

// One ConvLSTM step. Block = 8x8 pixel tile, 256 threads.
// Thread (pg, cg): pg = tid&15 -> 4 pixels {pg, pg+16, pg+32, pg+48} of the 64-pixel
// tile (same column, rows py0+2u); cg = tid>>4 -> filters fb..fb+3 (fb = cg*4),
// across all 4 gates (channels q*64+fb+j). 64 accumulators/thread.
// Each weight float4 load feeds 16 FMAs (4 pixels x 4 channels) -> FMA-bound.
__global__ __launch_bounds__(256, 2)
void step_kernel(const float* __restrict__ x,
                 const float* __restrict__ Wx,
                 const float* __restrict__ Wh,
                 const float* __restrict__ bias,
                 const float* __restrict__ h_in,
                 float* __restrict__ c_st,
                 float* __restrict__ h_out,
                 int t)
{
    __shared__ float sh[10 * 10 * SH_STRIDE];   // h halo tile, padded (27.2 KB)
    __shared__ float sx[10 * 10 * SX_STRIDE];   // x halo tile, padded (4.8 KB)

    const int tid = threadIdx.x;
    const int pg  = tid & 15;       // pixel group 0..15
    const int cg  = tid >> 4;       // filter quad 0..15
    const int fb  = cg * 4;         // filter base
    const int py0 = pg >> 3;        // 0..1
    const int px  = pg & 7;         // 0..7
    const int bx0 = blockIdx.x * 8;
    const int by0 = blockIdx.y * 8;
    const int bb  = blockIdx.z;

    // ---- stage h halo: 10x10 pixels x 64 ch = 1600 float4 ----
    for (int i = tid; i < 1600; i += 256) {
        int ch4 = i & 15;
        int pix = i >> 4;
        int r  = pix / 10;
        int cc = pix - r * 10;
        int gy = by0 + r - 1;
        int gx = bx0 + cc - 1;
        float4 v = make_float4(0.f, 0.f, 0.f, 0.f);
        if ((unsigned)gy < 96u && (unsigned)gx < 96u)
            v = __ldg((const float4*)(h_in + ((bb * 96 + gy) * 96 + gx) * 64 + ch4 * 4));
        *(float4*)(sh + pix * SH_STRIDE + ch4 * 4) = v;
    }
    // ---- stage x halo: 10x10 pixels x 8 ch = 200 float4 ----
    for (int i = tid; i < 200; i += 256) {
        int ch4 = i & 1;
        int pix = i >> 1;
        int r  = pix / 10;
        int cc = pix - r * 10;
        int gy = by0 + r - 1;
        int gx = bx0 + cc - 1;
        float4 v = make_float4(0.f, 0.f, 0.f, 0.f);
        if ((unsigned)gy < 96u && (unsigned)gx < 96u)
            v = __ldg((const float4*)(x + (((bb * TT + t) * 96 + gy) * 96 + gx) * 8 + ch4 * 4));
        *(float4*)(sx + pix * SX_STRIDE + ch4 * 4) = v;
    }
    __syncthreads();

    // acc[q][u] = float4 over 4 filters j, for gate q, pixel slot u
    float4 acc[4][4];
    #pragma unroll
    for (int q = 0; q < 4; q++) {
        float4 bv = __ldg((const float4*)(bias + q * 64 + fb));
        #pragma unroll
        for (int u = 0; u < 4; u++) acc[q][u] = bv;
    }

    // ---- input conv: K = 9 * 8 ----
    #pragma unroll 1
    for (int k = 0; k < 9; k++) {
        const int ky = k / 3;
        const int kx = k - ky * 3;
        const float* ab0 = sx + ((py0 + 0 + ky) * 10 + (px + kx)) * SX_STRIDE;
        const float* ab1 = ab0 + 2 * 10 * SX_STRIDE;
        const float* ab2 = ab1 + 2 * 10 * SX_STRIDE;
        const float* ab3 = ab2 + 2 * 10 * SX_STRIDE;
        const float* wkb = Wx + k * 8 * 256 + fb;
        #pragma unroll
        for (int ic0 = 0; ic0 < 8; ic0 += 4) {
            float4 av[4];
            av[0] = *(const float4*)(ab0 + ic0);
            av[1] = *(const float4*)(ab1 + ic0);
            av[2] = *(const float4*)(ab2 + ic0);
            av[3] = *(const float4*)(ab3 + ic0);
            #pragma unroll
            for (int v = 0; v < 4; v++) {
                const float* w = wkb + (ic0 + v) * 256;
                float4 w0 = __ldg((const float4*)(w));
                float4 w1 = __ldg((const float4*)(w + 64));
                float4 w2 = __ldg((const float4*)(w + 128));
                float4 w3 = __ldg((const float4*)(w + 192));
                #pragma unroll
                for (int u = 0; u < 4; u++) {
                    const float a = (v == 0) ? av[u].x : (v == 1) ? av[u].y
                                  : (v == 2) ? av[u].z : av[u].w;
                    acc[0][u].x = fmaf(a, w0.x, acc[0][u].x);
                    acc[0][u].y = fmaf(a, w0.y, acc[0][u].y);
                    acc[0][u].z = fmaf(a, w0.z, acc[0][u].z);
                    acc[0][u].w = fmaf(a, w0.w, acc[0][u].w);
                    acc[1][u].x = fmaf(a, w1.x, acc[1][u].x);
                    acc[1][u].y = fmaf(a, w1.y, acc[1][u].y);
                    acc[1][u].z = fmaf(a, w1.z, acc[1][u].z);
                    acc[1][u].w = fmaf(a, w1.w, acc[1][u].w);
                    acc[2][u].x = fmaf(a, w2.x, acc[2][u].x);
                    acc[2][u].y = fmaf(a, w2.y, acc[2][u].y);
                    acc[2][u].z = fmaf(a, w2.z, acc[2][u].z);
                    acc[2][u].w = fmaf(a, w2.w, acc[2][u].w);
                    acc[3][u].x = fmaf(a, w3.x, acc[3][u].x);
                    acc[3][u].y = fmaf(a, w3.y, acc[3][u].y);
                    acc[3][u].z = fmaf(a, w3.z, acc[3][u].z);
                    acc[3][u].w = fmaf(a, w3.w, acc[3][u].w);
                }
            }
        }
    }

    // ---- recurrent conv: K = 9 * 64 (dominant work) ----
    #pragma unroll 1
    for (int k = 0; k < 9; k++) {
        const int ky = k / 3;
        const int kx = k - ky * 3;
        const float* ab0 = sh + ((py0 + 0 + ky) * 10 + (px + kx)) * SH_STRIDE;
        const float* ab1 = ab0 + 2 * 10 * SH_STRIDE;
        const float* ab2 = ab1 + 2 * 10 * SH_STRIDE;
        const float* ab3 = ab2 + 2 * 10 * SH_STRIDE;
        const float* wkb = Wh + k * 64 * 256 + fb;
        #pragma unroll 2
        for (int ic0 = 0; ic0 < 64; ic0 += 4) {
            float4 av[4];
            av[0] = *(const float4*)(ab0 + ic0);
            av[1] = *(const float4*)(ab1 + ic0);
            av[2] = *(const float4*)(ab2 + ic0);
            av[3] = *(const float4*)(ab3 + ic0);
            #pragma unroll
            for (int v = 0; v < 4; v++) {
                const float* w = wkb + (ic0 + v) * 256;
                float4 w0 = __ldg((const float4*)(w));
                float4 w1 = __ldg((const float4*)(w + 64));
                float4 w2 = __ldg((const float4*)(w + 128));
                float4 w3 = __ldg((const float4*)(w + 192));
                #pragma unroll
                for (int u = 0; u < 4; u++) {
                    const float a = (v == 0) ? av[u].x : (v == 1) ? av[u].y
                                  : (v == 2) ? av[u].z : av[u].w;
                    acc[0][u].x = fmaf(a, w0.x, acc[0][u].x);
                    acc[0][u].y = fmaf(a, w0.y, acc[0][u].y);
                    acc[0][u].z = fmaf(a, w0.z, acc[0][u].z);
                    acc[0][u].w = fmaf(a, w0.w, acc[0][u].w);
                    acc[1][u].x = fmaf(a, w1.x, acc[1][u].x);
                    acc[1][u].y = fmaf(a, w1.y, acc[1][u].y);
                    acc[1][u].z = fmaf(a, w1.z, acc[1][u].z);
                    acc[1][u].w = fmaf(a, w1.w, acc[1][u].w);
                    acc[2][u].x = fmaf(a, w2.x, acc[2][u].x);
                    acc[2][u].y = fmaf(a, w2.y, acc[2][u].y);
                    acc[2][u].z = fmaf(a, w2.z, acc[2][u].z);
                    acc[2][u].w = fmaf(a, w2.w, acc[2][u].w);
                    acc[3][u].x = fmaf(a, w3.x, acc[3][u].x);
                    acc[3][u].y = fmaf(a, w3.y, acc[3][u].y);
                    acc[3][u].z = fmaf(a, w3.z, acc[3][u].z);
                    acc[3][u].w = fmaf(a, w3.w, acc[3][u].w);
                }
            }
        }
    }

    // ---- gate epilogue: i,f,g,o -> c_new, h_new (thread-local) ----
    #pragma unroll
    for (int u = 0; u < 4; u++) {
        const int gy = by0 + py0 + 2 * u;
        const int gx = bx0 + px;
        const int base = ((bb * 96 + gy) * 96 + gx) * 64 + fb;
        float4 cv = *(const float4*)(c_st + base);
        float cin[4] = {cv.x, cv.y, cv.z, cv.w};
        float iv[4] = {acc[0][u].x, acc[0][u].y, acc[0][u].z, acc[0][u].w};
        float fv[4] = {acc[1][u].x, acc[1][u].y, acc[1][u].z, acc[1][u].w};
        float gv[4] = {acc[2][u].x, acc[2][u].y, acc[2][u].z, acc[2][u].w};
        float ov[4] = {acc[3][u].x, acc[3][u].y, acc[3][u].z, acc[3][u].w};
        float cn[4], hn[4];
        #pragma unroll
        for (int j = 0; j < 4; j++) {
            float ig  = hsig(iv[j]);
            float fg_ = hsig(fv[j]);
            float gg  = tanhf(gv[j]);
            float og  = hsig(ov[j]);
            cn[j] = fg_ * cin[j] + ig * gg;
            hn[j] = og * tanhf(cn[j]);
        }
        *(float4*)(c_st + base)  = make_float4(cn[0], cn[1], cn[2], cn[3]);
        *(float4*)(h_out + base) = make_float4(hn[0], hn[1], hn[2], hn[3]);
    }
}

extern "C" void kernel_launch(void* const* d_in, const int* in_sizes, int n_in,
                              void* d_out, int out_size) {
    const float* x    = (const float*)d_in[0];
    const float* Wx   = (const float*)d_in[1];
    const float* Wh   = (const float*)d_in[2];
    const float* bias = (const float*)d_in[3];
    float* out = (float*)d_out;

    float *h0, *h1, *c;
    cudaGetSymbolAddress((void**)&h0, g_h0);
    cudaGetSymbolAddress((void**)&h1, g_h1);
    cudaGetSymbolAddress((void**)&c,  g_c);

    // zero h(0) and c(0) every call (graph replays must be deterministic)
    int n4 = NPIX / 4;
    zero_kernel<<<(n4 + 255) / 256, 256>>>(h0, c, n4);

    dim3 grid(12, 12, BB);   // 12x12 spatial tiles of 8x8, per batch
    for (int t = 0; t < TT; t++) {
        const float* hin = (t & 1) ? h1 : h0;
        float* hout = (t == TT - 1) ? out : ((t & 1) ? h0 : h1);
        step_kernel<<<grid, 256>>>(x, Wx, Wh, bias, hin, c, hout, t);
    }
}

// round 9
// speedup vs baseline: 1.6256x; 1.0004x over previous
#include <cuda_runtime.h>

#define BB 8
#define TT 16
#define HH 96
#define WW 96
#define CI 8
#define FF 64

#define NPIX (BB*HH*WW*FF)   // 4,718,592 floats per state buffer

#define SH_STRIDE 68         // 68 mod 32 == 4 -> conflict-free LDS.128 phases
#define SX_STRIDE 12         // 12 mod 32 -> conflict-free for 8-lane phases

__device__ float g_h0[NPIX];
__device__ float g_h1[NPIX];
__device__ float g_c[NPIX];

__device__ __forceinline__ float hsig(float z) {
    return fminf(fmaxf(fmaf(z, 0.2f, 0.5f), 0.0f), 1.0f);
}

__global__ void zero_kernel(float* a, float* b, int n4) {
    int i = blockIdx.x * blockDim.x + threadIdx.x;
    float4 z = make_float4(0.f, 0.f, 0.f, 0.f);
    if (i < n4) {
        ((float4*)a)[i] = z;
        ((float4*)b)[i] = z;
    }
}

// One ConvLSTM step. Block = 8x8 pixel tile, 256 threads.
// Thread (pg, cg): pg = tid&15 -> 4 pixels {pg, pg+16, pg+32, pg+48} of the 64-pixel
// tile (same column, rows py0+2u); cg = tid>>4 -> filters fb..fb+3 (fb = cg*4),
// across all 4 gates (channels q*64+fb+j). 64 accumulators/thread.
// Each weight float4 load feeds 16 FMAs (4 pixels x 4 channels) -> FMA-bound.
__global__ __launch_bounds__(256, 2)
void step_kernel(const float* __restrict__ x,
                 const float* __restrict__ Wx,
                 const float* __restrict__ Wh,
                 const float* __restrict__ bias,
                 const float* __restrict__ h_in,
                 float* __restrict__ c_st,
                 float* __restrict__ h_out,
                 int t)
{
    __shared__ float sh[10 * 10 * SH_STRIDE];   // h halo tile, padded (27.2 KB)
    __shared__ float sx[10 * 10 * SX_STRIDE];   // x halo tile, padded (4.8 KB)

    const int tid = threadIdx.x;
    const int pg  = tid & 15;       // pixel group 0..15
    const int cg  = tid >> 4;       // filter quad 0..15
    const int fb  = cg * 4;         // filter base
    const int py0 = pg >> 3;        // 0..1
    const int px  = pg & 7;         // 0..7
    const int bx0 = blockIdx.x * 8;
    const int by0 = blockIdx.y * 8;
    const int bb  = blockIdx.z;

    // ---- stage h halo: 10x10 pixels x 64 ch = 1600 float4 ----
    for (int i = tid; i < 1600; i += 256) {
        int ch4 = i & 15;
        int pix = i >> 4;
        int r  = pix / 10;
        int cc = pix - r * 10;
        int gy = by0 + r - 1;
        int gx = bx0 + cc - 1;
        float4 v = make_float4(0.f, 0.f, 0.f, 0.f);
        if ((unsigned)gy < 96u && (unsigned)gx < 96u)
            v = __ldg((const float4*)(h_in + ((bb * 96 + gy) * 96 + gx) * 64 + ch4 * 4));
        *(float4*)(sh + pix * SH_STRIDE + ch4 * 4) = v;
    }
    // ---- stage x halo: 10x10 pixels x 8 ch = 200 float4 ----
    for (int i = tid; i < 200; i += 256) {
        int ch4 = i & 1;
        int pix = i >> 1;
        int r  = pix / 10;
        int cc = pix - r * 10;
        int gy = by0 + r - 1;
        int gx = bx0 + cc - 1;
        float4 v = make_float4(0.f, 0.f, 0.f, 0.f);
        if ((unsigned)gy < 96u && (unsigned)gx < 96u)
            v = __ldg((const float4*)(x + (((bb * TT + t) * 96 + gy) * 96 + gx) * 8 + ch4 * 4));
        *(float4*)(sx + pix * SX_STRIDE + ch4 * 4) = v;
    }
    __syncthreads();

    // acc[q][u] = float4 over 4 filters j, for gate q, pixel slot u
    float4 acc[4][4];
    #pragma unroll
    for (int q = 0; q < 4; q++) {
        float4 bv = __ldg((const float4*)(bias + q * 64 + fb));
        #pragma unroll
        for (int u = 0; u < 4; u++) acc[q][u] = bv;
    }

    // ---- input conv: K = 9 * 8 ----
    #pragma unroll 1
    for (int k = 0; k < 9; k++) {
        const int ky = k / 3;
        const int kx = k - ky * 3;
        const float* ab0 = sx + ((py0 + 0 + ky) * 10 + (px + kx)) * SX_STRIDE;
        const float* ab1 = ab0 + 2 * 10 * SX_STRIDE;
        const float* ab2 = ab1 + 2 * 10 * SX_STRIDE;
        const float* ab3 = ab2 + 2 * 10 * SX_STRIDE;
        const float* wkb = Wx + k * 8 * 256 + fb;
        #pragma unroll
        for (int ic0 = 0; ic0 < 8; ic0 += 4) {
            float4 av[4];
            av[0] = *(const float4*)(ab0 + ic0);
            av[1] = *(const float4*)(ab1 + ic0);
            av[2] = *(const float4*)(ab2 + ic0);
            av[3] = *(const float4*)(ab3 + ic0);
            #pragma unroll
            for (int v = 0; v < 4; v++) {
                const float* w = wkb + (ic0 + v) * 256;
                float4 w0 = __ldg((const float4*)(w));
                float4 w1 = __ldg((const float4*)(w + 64));
                float4 w2 = __ldg((const float4*)(w + 128));
                float4 w3 = __ldg((const float4*)(w + 192));
                #pragma unroll
                for (int u = 0; u < 4; u++) {
                    const float a = (v == 0) ? av[u].x : (v == 1) ? av[u].y
                                  : (v == 2) ? av[u].z : av[u].w;
                    acc[0][u].x = fmaf(a, w0.x, acc[0][u].x);
                    acc[0][u].y = fmaf(a, w0.y, acc[0][u].y);
                    acc[0][u].z = fmaf(a, w0.z, acc[0][u].z);
                    acc[0][u].w = fmaf(a, w0.w, acc[0][u].w);
                    acc[1][u].x = fmaf(a, w1.x, acc[1][u].x);
                    acc[1][u].y = fmaf(a, w1.y, acc[1][u].y);
                    acc[1][u].z = fmaf(a, w1.z, acc[1][u].z);
                    acc[1][u].w = fmaf(a, w1.w, acc[1][u].w);
                    acc[2][u].x = fmaf(a, w2.x, acc[2][u].x);
                    acc[2][u].y = fmaf(a, w2.y, acc[2][u].y);
                    acc[2][u].z = fmaf(a, w2.z, acc[2][u].z);
                    acc[2][u].w = fmaf(a, w2.w, acc[2][u].w);
                    acc[3][u].x = fmaf(a, w3.x, acc[3][u].x);
                    acc[3][u].y = fmaf(a, w3.y, acc[3][u].y);
                    acc[3][u].z = fmaf(a, w3.z, acc[3][u].z);
                    acc[3][u].w = fmaf(a, w3.w, acc[3][u].w);
                }
            }
        }
    }

    // ---- recurrent conv: K = 9 * 64 (dominant work) ----
    #pragma unroll 1
    for (int k = 0; k < 9; k++) {
        const int ky = k / 3;
        const int kx = k - ky * 3;
        const float* ab0 = sh + ((py0 + 0 + ky) * 10 + (px + kx)) * SH_STRIDE;
        const float* ab1 = ab0 + 2 * 10 * SH_STRIDE;
        const float* ab2 = ab1 + 2 * 10 * SH_STRIDE;
        const float* ab3 = ab2 + 2 * 10 * SH_STRIDE;
        const float* wkb = Wh + k * 64 * 256 + fb;
        #pragma unroll 2
        for (int ic0 = 0; ic0 < 64; ic0 += 4) {
            float4 av[4];
            av[0] = *(const float4*)(ab0 + ic0);
            av[1] = *(const float4*)(ab1 + ic0);
            av[2] = *(const float4*)(ab2 + ic0);
            av[3] = *(const float4*)(ab3 + ic0);
            #pragma unroll
            for (int v = 0; v < 4; v++) {
                const float* w = wkb + (ic0 + v) * 256;
                float4 w0 = __ldg((const float4*)(w));
                float4 w1 = __ldg((const float4*)(w + 64));
                float4 w2 = __ldg((const float4*)(w + 128));
                float4 w3 = __ldg((const float4*)(w + 192));
                #pragma unroll
                for (int u = 0; u < 4; u++) {
                    const float a = (v == 0) ? av[u].x : (v == 1) ? av[u].y
                                  : (v == 2) ? av[u].z : av[u].w;
                    acc[0][u].x = fmaf(a, w0.x, acc[0][u].x);
                    acc[0][u].y = fmaf(a, w0.y, acc[0][u].y);
                    acc[0][u].z = fmaf(a, w0.z, acc[0][u].z);
                    acc[0][u].w = fmaf(a, w0.w, acc[0][u].w);
                    acc[1][u].x = fmaf(a, w1.x, acc[1][u].x);
                    acc[1][u].y = fmaf(a, w1.y, acc[1][u].y);
                    acc[1][u].z = fmaf(a, w1.z, acc[1][u].z);
                    acc[1][u].w = fmaf(a, w1.w, acc[1][u].w);
                    acc[2][u].x = fmaf(a, w2.x, acc[2][u].x);
                    acc[2][u].y = fmaf(a, w2.y, acc[2][u].y);
                    acc[2][u].z = fmaf(a, w2.z, acc[2][u].z);
                    acc[2][u].w = fmaf(a, w2.w, acc[2][u].w);
                    acc[3][u].x = fmaf(a, w3.x, acc[3][u].x);
                    acc[3][u].y = fmaf(a, w3.y, acc[3][u].y);
                    acc[3][u].z = fmaf(a, w3.z, acc[3][u].z);
                    acc[3][u].w = fmaf(a, w3.w, acc[3][u].w);
                }
            }
        }
    }

    // ---- gate epilogue: i,f,g,o -> c_new, h_new (thread-local) ----
    #pragma unroll
    for (int u = 0; u < 4; u++) {
        const int gy = by0 + py0 + 2 * u;
        const int gx = bx0 + px;
        const int base = ((bb * 96 + gy) * 96 + gx) * 64 + fb;
        float4 cv = *(const float4*)(c_st + base);
        float cin[4] = {cv.x, cv.y, cv.z, cv.w};
        float iv[4] = {acc[0][u].x, acc[0][u].y, acc[0][u].z, acc[0][u].w};
        float fv[4] = {acc[1][u].x, acc[1][u].y, acc[1][u].z, acc[1][u].w};
        float gv[4] = {acc[2][u].x, acc[2][u].y, acc[2][u].z, acc[2][u].w};
        float ov[4] = {acc[3][u].x, acc[3][u].y, acc[3][u].z, acc[3][u].w};
        float cn[4], hn[4];
        #pragma unroll
        for (int j = 0; j < 4; j++) {
            float ig  = hsig(iv[j]);
            float fg_ = hsig(fv[j]);
            float gg  = tanhf(gv[j]);
            float og  = hsig(ov[j]);
            cn[j] = fg_ * cin[j] + ig * gg;
            hn[j] = og * tanhf(cn[j]);
        }
        *(float4*)(c_st + base)  = make_float4(cn[0], cn[1], cn[2], cn[3]);
        *(float4*)(h_out + base) = make_float4(hn[0], hn[1], hn[2], hn[3]);
    }
}

extern "C" void kernel_launch(void* const* d_in, const int* in_sizes, int n_in,
                              void* d_out, int out_size) {
    const float* x    = (const float*)d_in[0];
    const float* Wx   = (const float*)d_in[1];
    const float* Wh   = (const float*)d_in[2];
    const float* bias = (const float*)d_in[3];
    float* out = (float*)d_out;

    float *h0, *h1, *c;
    cudaGetSymbolAddress((void**)&h0, g_h0);
    cudaGetSymbolAddress((void**)&h1, g_h1);
    cudaGetSymbolAddress((void**)&c,  g_c);

    // zero h(0) and c(0) every call (graph replays must be deterministic)
    int n4 = NPIX / 4;
    zero_kernel<<<(n4 + 255) / 256, 256>>>(h0, c, n4);

    dim3 grid(12, 12, BB);   // 12x12 spatial tiles of 8x8, per batch
    for (int t = 0; t < TT; t++) {
        const float* hin = (t & 1) ? h1 : h0;
        float* hout = (t == TT - 1) ? out : ((t & 1) ? h0 : h1);
        step_kernel<<<grid, 256>>>(x, Wx, Wh, bias, hin, c, hout, t);
    }
}